// round 3
// baseline (speedup 1.0000x reference)
#include <cuda_runtime.h>

// TRFAligner: out[d, t] = sum over (seq, k) with sourceIdx[seq] + k == t of TRFs[seq, k, d]
// TRFs: (nSeq, nWin, OUTD) fp32; out: (OUTD, nRealLen) fp32.
// sourceIdx sorted -> tile timeline (64 t per CTA), binary-search overlapping seqs,
// accumulate in registers (8 rows/warp, static ownership), immediate-offset batched
// LDG.128 loads, one smem transpose at the end. No atomics.

#define OUTD      128
#define TILE_T    64
#define ROWPAD    4
#define ROWSTRIDE (OUTD + ROWPAD)     // 132 floats
#define NWARPS    8
#define NTHREADS  (NWARPS * 32)
#define ROWS_PW   (TILE_T / NWARPS)   // 8 rows per warp

__global__ __launch_bounds__(NTHREADS) void trf_fold_kernel(
    const float* __restrict__ TRFs,
    const int*   __restrict__ sIdx,
    float*       __restrict__ out,
    int nSeq, int nWin, int nRealLen)
{
    __shared__ float sm[TILE_T * ROWSTRIDE];

    const int t0      = blockIdx.x * TILE_T;
    const int tEnd    = min(t0 + TILE_T, nRealLen);
    const int tileLen = tEnd - t0;
    const int tid     = threadIdx.x;
    const int w       = tid >> 5;
    const int lane    = tid & 31;

    // ---- binary search seq range overlapping [t0, tEnd): sIdx in [t0-nWin+1, tEnd-1] ----
    int seqLo, seqHi;
    {
        int lo = 0, hi = nSeq, thr = t0 - nWin + 1;
        while (lo < hi) { int m = (lo + hi) >> 1; if (sIdx[m] < thr) lo = m + 1; else hi = m; }
        seqLo = lo;
        hi = nSeq;
        while (lo < hi) { int m = (lo + hi) >> 1; if (sIdx[m] < tEnd) lo = m + 1; else hi = m; }
        seqHi = lo;
    }

    // ---- register accumulation: warp owns rows tt = w + 8*r ----
    float4 acc[ROWS_PW];
    #pragma unroll
    for (int r = 0; r < ROWS_PW; ++r) acc[r] = make_float4(0.f, 0.f, 0.f, 0.f);

    if (seqLo < seqHi) {
        int s = sIdx[seqLo];                        // prefetched onset
        for (int i = seqLo; i < seqHi; ++i) {
            const int sNext = (i + 1 < seqHi) ? sIdx[i + 1] : 0;
            const int kb = t0 + w - s;              // k for row r is kb + 8*r
            // single base pointer; row r at compile-time byte offset r*4096
            const float4* __restrict__ base =
                reinterpret_cast<const float4*>(TRFs)
                + ((long)i * nWin + kb) * (OUTD / 4) + lane;
            #pragma unroll
            for (int r = 0; r < ROWS_PW; ++r) {
                if ((unsigned)(kb + 8 * r) < (unsigned)nWin) {
                    float4 v = base[r * 8 * (OUTD / 4)];   // LDG.128 [R+imm]
                    acc[r].x += v.x; acc[r].y += v.y;
                    acc[r].z += v.z; acc[r].w += v.w;
                }
            }
            s = sNext;
        }
    }

    // ---- one smem pass for the transpose ----
    #pragma unroll
    for (int r = 0; r < ROWS_PW; ++r)
        *reinterpret_cast<float4*>(sm + (w + 8 * r) * ROWSTRIDE + lane * 4) = acc[r];
    __syncthreads();

    // ---- coalesced store: consecutive tid -> consecutive t within each d-row ----
    #pragma unroll
    for (int idx = tid; idx < OUTD * TILE_T; idx += NTHREADS) {
        const int d  = idx >> 6;            // / TILE_T
        const int tt = idx & (TILE_T - 1);
        if (tt < tileLen)
            out[(size_t)d * nRealLen + t0 + tt] = sm[tt * ROWSTRIDE + d];
    }
}

extern "C" void kernel_launch(void* const* d_in, const int* in_sizes, int n_in,
                              void* d_out, int out_size)
{
    const float* TRFs = (const float*)d_in[0];
    const int*   sIdx = (const int*)d_in[1];
    const int nSeq     = in_sizes[1];
    const int nWin     = in_sizes[0] / (nSeq * OUTD);
    const int nRealLen = out_size / OUTD;

    const int grid = (nRealLen + TILE_T - 1) / TILE_T;
    trf_fold_kernel<<<grid, NTHREADS>>>(TRFs, sIdx, (float*)d_out,
                                        nSeq, nWin, nRealLen);
}

// round 4
// speedup vs baseline: 1.3007x; 1.3007x over previous
#include <cuda_runtime.h>

// TRFAligner: out[d, t] = sum over (seq, k) with sourceIdx[seq] + k == t of TRFs[seq, k, d]
// TRFs: (nSeq, nWin, OUTD) fp32; out: (OUTD, nRealLen) fp32.
// sourceIdx sorted -> tile timeline (32 t / CTA, zero read redundancy), binary-search
// overlapping seqs, onsets cached in smem, REGISTER accumulation (4 rows/warp, 16 regs),
// forced 8 CTAs/SM for 100% occupancy. No atomics.

#define OUTD      128
#define TILE_T    32
#define ROWSTRIDE 132                 // (OUTD+4) floats, odd-16B rows kept 16B-aligned
#define NWARPS    8
#define NTHREADS  (NWARPS * 32)
#define ROWS_PW   (TILE_T / NWARPS)   // 4 rows per warp: tt = w + 8*r
#define CHUNK     64

__global__ __launch_bounds__(NTHREADS, 8) void trf_fold_kernel(
    const float4* __restrict__ TRF4,
    const int*    __restrict__ sIdx,
    float*        __restrict__ out,
    int nSeq, int nWin, int nRealLen)
{
    __shared__ float sm[TILE_T * ROWSTRIDE];
    __shared__ int   s_on[CHUNK];

    const int t0   = blockIdx.x * TILE_T;
    const int tid  = threadIdx.x;
    const int w    = tid >> 5;
    const int lane = tid & 31;

    // ---- binary search seq range overlapping [t0, t0+TILE_T): sIdx in [t0-nWin+1, t0+TILE_T-1]
    int seqLo, seqHi;
    {
        int lo = 0, hi = nSeq, thr = t0 - nWin + 1;
        while (lo < hi) { int m = (lo + hi) >> 1; if (sIdx[m] < thr) lo = m + 1; else hi = m; }
        seqLo = lo;
        hi = nSeq;
        const int thr2 = t0 + TILE_T;
        while (lo < hi) { int m = (lo + hi) >> 1; if (sIdx[m] < thr2) lo = m + 1; else hi = m; }
        seqHi = lo;
    }

    // ---- register accumulation: warp owns rows tt = w + 8*r ----
    float4 acc[ROWS_PW];
    #pragma unroll
    for (int r = 0; r < ROWS_PW; ++r) acc[r] = make_float4(0.f, 0.f, 0.f, 0.f);

    const unsigned f4Row     = OUTD / 4;                      // 32 float4 per row
    const unsigned seqStride = (unsigned)nWin * f4Row;        // float4 per seq

    for (int cbase = seqLo; cbase < seqHi; cbase += CHUNK) {
        const int cn = min(seqHi - cbase, CHUNK);
        __syncthreads();                                      // protect s_on reuse
        if (tid < cn) s_on[tid] = sIdx[cbase + tid];
        __syncthreads();

        for (int j = 0; j < cn; ++j) {
            const int s  = s_on[j];                           // smem broadcast
            const int kb = t0 + w - s;                        // k for row r: kb + 8r
            // 32-bit element offset (TRFs < 2^28 floats); modular arith is exact
            // whenever the predicate holds.
            const unsigned off = (unsigned)(cbase + j) * seqStride
                               + (unsigned)kb * f4Row + (unsigned)lane;
            #pragma unroll
            for (int r = 0; r < ROWS_PW; ++r) {
                if ((unsigned)(kb + 8 * r) < (unsigned)nWin) {
                    float4 v = TRF4[off + r * 8 * f4Row];     // LDG.128 [R+imm]
                    acc[r].x += v.x; acc[r].y += v.y;
                    acc[r].z += v.z; acc[r].w += v.w;
                }
            }
        }
    }

    // ---- one smem pass for the transpose ----
    #pragma unroll
    for (int r = 0; r < ROWS_PW; ++r)
        *reinterpret_cast<float4*>(sm + (w + 8 * r) * ROWSTRIDE + lane * 4) = acc[r];
    __syncthreads();

    // ---- coalesced store: consecutive tid -> consecutive t within each d-row ----
    #pragma unroll
    for (int idx = tid; idx < OUTD * TILE_T; idx += NTHREADS) {
        const int d  = idx >> 5;              // / TILE_T
        const int tt = idx & (TILE_T - 1);
        const int t  = t0 + tt;
        if (t < nRealLen)
            out[(size_t)d * nRealLen + t] = sm[tt * ROWSTRIDE + d];
    }
}

extern "C" void kernel_launch(void* const* d_in, const int* in_sizes, int n_in,
                              void* d_out, int out_size)
{
    const float4* TRF4 = (const float4*)d_in[0];
    const int*    sIdx = (const int*)d_in[1];
    const int nSeq     = in_sizes[1];
    const int nWin     = in_sizes[0] / (nSeq * OUTD);
    const int nRealLen = out_size / OUTD;

    const int grid = (nRealLen + TILE_T - 1) / TILE_T;
    trf_fold_kernel<<<grid, NTHREADS>>>(TRF4, sIdx, (float*)d_out,
                                        nSeq, nWin, nRealLen);
}

// round 5
// speedup vs baseline: 1.4042x; 1.0796x over previous
#include <cuda_runtime.h>

// TRFAligner: out[d, t] = sum over (seq, k) with sourceIdx[seq] + k == t of TRFs[seq, k, d]
// TRFs: (nSeq, nWin, OUTD) fp32; out: (OUTD, nRealLen) fp32. sourceIdx sorted.
// Two kernels: (1) parallel binary-search of per-tile seq ranges into device scratch,
// (2) fold kernel: register accumulation (4 rows/warp), onset prefetch, smem transpose.
// No atomics, no serial per-CTA binary search.

#define OUTD      128
#define TILE_T    32
#define ROWSTRIDE 132                 // (OUTD+4) floats, float4-aligned rows
#define NWARPS    8
#define NTHREADS  (NWARPS * 32)
#define ROWS_PW   (TILE_T / NWARPS)   // 4 rows per warp: tt = w + 8*r
#define CHUNK     64
#define MAXTILES  8192

__device__ int g_tileLo[MAXTILES];
__device__ int g_tileHi[MAXTILES];

__device__ __forceinline__ int lower_bound_dev(const int* __restrict__ a, int n, int v)
{
    int lo = 0, hi = n;
    while (lo < hi) { int m = (lo + hi) >> 1; if (a[m] < v) lo = m + 1; else hi = m; }
    return lo;
}

__global__ void tile_ranges_kernel(const int* __restrict__ sIdx,
                                   int nSeq, int nWin, int nTiles)
{
    int i = blockIdx.x * blockDim.x + threadIdx.x;
    if (i >= nTiles) return;
    const int t0 = i * TILE_T;
    g_tileLo[i] = lower_bound_dev(sIdx, nSeq, t0 - nWin + 1);
    g_tileHi[i] = lower_bound_dev(sIdx, nSeq, t0 + TILE_T);
}

__global__ __launch_bounds__(NTHREADS, 8) void trf_fold_kernel(
    const float4* __restrict__ TRF4,
    const int*    __restrict__ sIdx,
    float*        __restrict__ out,
    int nSeq, int nWin, int nRealLen)
{
    __shared__ float sm[TILE_T * ROWSTRIDE];
    __shared__ int   s_on[CHUNK];

    const int t0   = blockIdx.x * TILE_T;
    const int tid  = threadIdx.x;
    const int w    = tid >> 5;
    const int lane = tid & 31;

    const int seqLo = g_tileLo[blockIdx.x];
    const int seqHi = g_tileHi[blockIdx.x];

    float4 acc[ROWS_PW];
    #pragma unroll
    for (int r = 0; r < ROWS_PW; ++r) acc[r] = make_float4(0.f, 0.f, 0.f, 0.f);

    const unsigned f4Row     = OUTD / 4;                 // 32 float4 per row
    const unsigned seqStride = (unsigned)nWin * f4Row;   // float4 per seq

    for (int cbase = seqLo; cbase < seqHi; cbase += CHUNK) {
        const int cn = min(seqHi - cbase, CHUNK);
        __syncthreads();                                 // protect s_on reuse
        if (tid < cn) s_on[tid] = sIdx[cbase + tid];
        __syncthreads();

        int s = s_on[0];                                 // prefetched onset
        for (int j = 0; j < cn; ++j) {
            const int sNext = (j + 1 < cn) ? s_on[j + 1] : 0;   // LDS off critical path
            const int kb = t0 + w - s;                   // k for row r: kb + 8r
            const unsigned off = (unsigned)(cbase + j) * seqStride
                               + (unsigned)kb * f4Row + (unsigned)lane;
            #pragma unroll
            for (int r = 0; r < ROWS_PW; ++r) {
                if ((unsigned)(kb + 8 * r) < (unsigned)nWin) {
                    float4 v = TRF4[off + r * 8 * f4Row];       // LDG.128 [R+imm]
                    acc[r].x += v.x; acc[r].y += v.y;
                    acc[r].z += v.z; acc[r].w += v.w;
                }
            }
            s = sNext;
        }
    }

    // ---- one smem pass for the transpose ----
    #pragma unroll
    for (int r = 0; r < ROWS_PW; ++r)
        *reinterpret_cast<float4*>(sm + (w + 8 * r) * ROWSTRIDE + lane * 4) = acc[r];
    __syncthreads();

    // ---- coalesced store: consecutive tid -> consecutive t within each d-row ----
    #pragma unroll
    for (int idx = tid; idx < OUTD * TILE_T; idx += NTHREADS) {
        const int d  = idx >> 5;              // / TILE_T
        const int tt = idx & (TILE_T - 1);
        const int t  = t0 + tt;
        if (t < nRealLen)
            out[(size_t)d * nRealLen + t] = sm[tt * ROWSTRIDE + d];
    }
}

extern "C" void kernel_launch(void* const* d_in, const int* in_sizes, int n_in,
                              void* d_out, int out_size)
{
    const float4* TRF4 = (const float4*)d_in[0];
    const int*    sIdx = (const int*)d_in[1];
    const int nSeq     = in_sizes[1];
    const int nWin     = in_sizes[0] / (nSeq * OUTD);
    const int nRealLen = out_size / OUTD;

    int grid = (nRealLen + TILE_T - 1) / TILE_T;
    if (grid > MAXTILES) grid = MAXTILES;   // shapes here: 3125 << 8192

    tile_ranges_kernel<<<(grid + 255) / 256, 256>>>(sIdx, nSeq, nWin, grid);
    trf_fold_kernel<<<grid, NTHREADS>>>(TRF4, sIdx, (float*)d_out,
                                        nSeq, nWin, nRealLen);
}

// round 6
// speedup vs baseline: 1.4560x; 1.0369x over previous
#include <cuda_runtime.h>

// TRFAligner: out[d, t] = sum over (seq, k) with sourceIdx[seq] + k == t of TRFs[seq, k, d]
// TRFs: (nSeq, nWin, OUTD) fp32; out: (OUTD, nRealLen) fp32. sourceIdx sorted.
// Kernel 1: per-tile seq ranges via SMEM-resident binary search (sIdx fits in 16KB).
// Kernel 2: fold; register accumulation (4 rows/warp), onset prefetch, smem transpose.
// No atomics.

#define OUTD      128
#define TILE_T    32
#define ROWSTRIDE 132                 // (OUTD+4) floats, float4-aligned rows
#define NWARPS    8
#define NTHREADS  (NWARPS * 32)
#define ROWS_PW   (TILE_T / NWARPS)   // 4 rows per warp: tt = w + 8*r
#define CHUNK     64
#define MAXTILES  8192
#define MAXSEQ    8192                // smem budget for sorted onsets (32KB)

__device__ int g_tileLo[MAXTILES];
__device__ int g_tileHi[MAXTILES];

// ---- Kernel 1: ranges. Each CTA caches all onsets in smem, threads search smem. ----
__global__ __launch_bounds__(256) void tile_ranges_kernel(
    const int* __restrict__ sIdx, int nSeq, int nWin, int nTiles)
{
    __shared__ int s_all[MAXSEQ];
    const int n = min(nSeq, MAXSEQ);
    for (int i = threadIdx.x; i < n; i += blockDim.x) s_all[i] = sIdx[i];
    __syncthreads();

    const int i = blockIdx.x * blockDim.x + threadIdx.x;
    if (i >= nTiles) return;
    const int t0 = i * TILE_T;

    int lo = 0, hi = n, thr = t0 - nWin + 1;
    while (lo < hi) { int m = (lo + hi) >> 1; if (s_all[m] < thr) lo = m + 1; else hi = m; }
    g_tileLo[i] = lo;
    hi = n; thr = t0 + TILE_T;
    while (lo < hi) { int m = (lo + hi) >> 1; if (s_all[m] < thr) lo = m + 1; else hi = m; }
    g_tileHi[i] = lo;
}

// ---- Kernel 2: fold ----
__global__ __launch_bounds__(NTHREADS, 8) void trf_fold_kernel(
    const float4* __restrict__ TRF4,
    const int*    __restrict__ sIdx,
    float*        __restrict__ out,
    int nSeq, int nWin, int nRealLen)
{
    __shared__ float sm[TILE_T * ROWSTRIDE];
    __shared__ int   s_on[CHUNK];

    const int t0   = blockIdx.x * TILE_T;
    const int tid  = threadIdx.x;
    const int w    = tid >> 5;
    const int lane = tid & 31;

    const int seqLo = g_tileLo[blockIdx.x];
    const int seqHi = g_tileHi[blockIdx.x];

    float4 acc[ROWS_PW];
    #pragma unroll
    for (int r = 0; r < ROWS_PW; ++r) acc[r] = make_float4(0.f, 0.f, 0.f, 0.f);

    const unsigned f4Row     = OUTD / 4;                 // 32 float4 per row
    const unsigned seqStride = (unsigned)nWin * f4Row;   // float4 per seq

    for (int cbase = seqLo; cbase < seqHi; cbase += CHUNK) {
        const int cn = min(seqHi - cbase, CHUNK);
        __syncthreads();                                 // protect s_on reuse
        if (tid < cn) s_on[tid] = sIdx[cbase + tid];
        __syncthreads();

        int s = s_on[0];                                 // prefetched onset
        for (int j = 0; j < cn; ++j) {
            const int sNext = (j + 1 < cn) ? s_on[j + 1] : 0;   // LDS off critical path
            const int kb = t0 + w - s;                   // k for row r: kb + 8r
            const unsigned off = (unsigned)(cbase + j) * seqStride
                               + (unsigned)kb * f4Row + (unsigned)lane;
            #pragma unroll
            for (int r = 0; r < ROWS_PW; ++r) {
                if ((unsigned)(kb + 8 * r) < (unsigned)nWin) {
                    float4 v = TRF4[off + r * 8 * f4Row];       // LDG.128 [R+imm]
                    acc[r].x += v.x; acc[r].y += v.y;
                    acc[r].z += v.z; acc[r].w += v.w;
                }
            }
            s = sNext;
        }
    }

    // ---- one smem pass for the transpose ----
    #pragma unroll
    for (int r = 0; r < ROWS_PW; ++r)
        *reinterpret_cast<float4*>(sm + (w + 8 * r) * ROWSTRIDE + lane * 4) = acc[r];
    __syncthreads();

    // ---- coalesced store: consecutive tid -> consecutive t within each d-row ----
    #pragma unroll
    for (int idx = tid; idx < OUTD * TILE_T; idx += NTHREADS) {
        const int d  = idx >> 5;              // / TILE_T
        const int tt = idx & (TILE_T - 1);
        const int t  = t0 + tt;
        if (t < nRealLen)
            out[(size_t)d * nRealLen + t] = sm[tt * ROWSTRIDE + d];
    }
}

extern "C" void kernel_launch(void* const* d_in, const int* in_sizes, int n_in,
                              void* d_out, int out_size)
{
    const float4* TRF4 = (const float4*)d_in[0];
    const int*    sIdx = (const int*)d_in[1];
    const int nSeq     = in_sizes[1];
    const int nWin     = in_sizes[0] / (nSeq * OUTD);
    const int nRealLen = out_size / OUTD;

    int grid = (nRealLen + TILE_T - 1) / TILE_T;
    if (grid > MAXTILES) grid = MAXTILES;   // shapes here: 3125 << 8192

    tile_ranges_kernel<<<(grid + 255) / 256, 256>>>(sIdx, nSeq, nWin, grid);
    trf_fold_kernel<<<grid, NTHREADS>>>(TRF4, sIdx, (float*)d_out,
                                        nSeq, nWin, nRealLen);
}

// round 7
// speedup vs baseline: 1.5005x; 1.0305x over previous
#include <cuda_runtime.h>

// TRFAligner: out[d, t] = sum over (seq, k) with sourceIdx[seq] + k == t of TRFs[seq, k, d]
// TRFs: (nSeq, nWin, OUTD) fp32; out: (OUTD, nRealLen) fp32. sourceIdx sorted.
// Single kernel. Per-CTA seq range via warp-cooperative 32-ary ballot search
// (~3 rounds instead of ~24 serial steps). Register accumulation (4 rows/warp),
// onset prefetch, smem transpose. No atomics.

#define OUTD      128
#define TILE_T    32
#define ROWSTRIDE 132                 // (OUTD+4) floats, float4-aligned rows
#define NWARPS    8
#define NTHREADS  (NWARPS * 32)
#define ROWS_PW   (TILE_T / NWARPS)   // 4 rows per warp: tt = w + 8*r
#define CHUNK     64

// Warp-cooperative lower_bound: smallest i with a[i] >= v. All 32 lanes participate.
__device__ __forceinline__ int warp_lower_bound(const int* __restrict__ a,
                                                int n, int v, int lane)
{
    int lo = 0, hi = n;                       // answer in [lo, hi]
    while (hi - lo > 32) {
        const int chunk = (hi - lo + 32) / 33;
        const int p  = lo + (lane + 1) * chunk;
        const int pv = (p < hi) ? a[p] : 0x7fffffff;
        const unsigned m = __ballot_sync(0xffffffffu, pv < v);
        const int c = __popc(m);              // probes strictly below v
        const int nlo = lo + c * chunk;
        hi = min(hi, nlo + chunk);
        lo = nlo;
    }
    const int p  = lo + lane;
    const int pv = (p < hi) ? a[p] : 0x7fffffff;
    const unsigned m = __ballot_sync(0xffffffffu, pv < v);
    return lo + __popc(m);
}

__global__ __launch_bounds__(NTHREADS, 8) void trf_fold_kernel(
    const float4* __restrict__ TRF4,
    const int*    __restrict__ sIdx,
    float*        __restrict__ out,
    int nSeq, int nWin, int nRealLen)
{
    __shared__ float sm[TILE_T * ROWSTRIDE];
    __shared__ int   s_on[CHUNK];
    __shared__ int   s_range[2];

    const int t0   = blockIdx.x * TILE_T;
    const int tid  = threadIdx.x;
    const int w    = tid >> 5;
    const int lane = tid & 31;

    // ---- per-CTA range: warps 0 and 1 search concurrently (~3 ballot rounds each)
    if (w == 0) {
        int lo = warp_lower_bound(sIdx, nSeq, t0 - nWin + 1, lane);
        if (lane == 0) s_range[0] = lo;
    } else if (w == 1) {
        int hi = warp_lower_bound(sIdx, nSeq, t0 + TILE_T, lane);
        if (lane == 0) s_range[1] = hi;
    }
    __syncthreads();
    const int seqLo = s_range[0];
    const int seqHi = s_range[1];

    float4 acc[ROWS_PW];
    #pragma unroll
    for (int r = 0; r < ROWS_PW; ++r) acc[r] = make_float4(0.f, 0.f, 0.f, 0.f);

    const unsigned f4Row     = OUTD / 4;                 // 32 float4 per row
    const unsigned seqStride = (unsigned)nWin * f4Row;   // float4 per seq

    for (int cbase = seqLo; cbase < seqHi; cbase += CHUNK) {
        const int cn = min(seqHi - cbase, CHUNK);
        __syncthreads();                                 // protect s_on reuse
        if (tid < cn) s_on[tid] = sIdx[cbase + tid];
        __syncthreads();

        int s = s_on[0];                                 // prefetched onset
        for (int j = 0; j < cn; ++j) {
            const int sNext = (j + 1 < cn) ? s_on[j + 1] : 0;   // LDS off critical path
            const int kb = t0 + w - s;                   // k for row r: kb + 8r
            const unsigned off = (unsigned)(cbase + j) * seqStride
                               + (unsigned)kb * f4Row + (unsigned)lane;
            #pragma unroll
            for (int r = 0; r < ROWS_PW; ++r) {
                if ((unsigned)(kb + 8 * r) < (unsigned)nWin) {
                    float4 v = TRF4[off + r * 8 * f4Row];       // LDG.128 [R+imm]
                    acc[r].x += v.x; acc[r].y += v.y;
                    acc[r].z += v.z; acc[r].w += v.w;
                }
            }
            s = sNext;
        }
    }

    // ---- one smem pass for the transpose ----
    #pragma unroll
    for (int r = 0; r < ROWS_PW; ++r)
        *reinterpret_cast<float4*>(sm + (w + 8 * r) * ROWSTRIDE + lane * 4) = acc[r];
    __syncthreads();

    // ---- coalesced store: consecutive tid -> consecutive t within each d-row ----
    #pragma unroll
    for (int idx = tid; idx < OUTD * TILE_T; idx += NTHREADS) {
        const int d  = idx >> 5;              // / TILE_T
        const int tt = idx & (TILE_T - 1);
        const int t  = t0 + tt;
        if (t < nRealLen)
            out[(size_t)d * nRealLen + t] = sm[tt * ROWSTRIDE + d];
    }
}

extern "C" void kernel_launch(void* const* d_in, const int* in_sizes, int n_in,
                              void* d_out, int out_size)
{
    const float4* TRF4 = (const float4*)d_in[0];
    const int*    sIdx = (const int*)d_in[1];
    const int nSeq     = in_sizes[1];
    const int nWin     = in_sizes[0] / (nSeq * OUTD);
    const int nRealLen = out_size / OUTD;

    const int grid = (nRealLen + TILE_T - 1) / TILE_T;
    trf_fold_kernel<<<grid, NTHREADS>>>(TRF4, sIdx, (float*)d_out,
                                        nSeq, nWin, nRealLen);
}

// round 8
// speedup vs baseline: 1.5494x; 1.0326x over previous
#include <cuda_runtime.h>

// TRFAligner: out[d, t] = sum over (seq, k) with sourceIdx[seq] + k == t of TRFs[seq, k, d]
// TRFs: (nSeq, nWin, OUTD) fp32; out: (OUTD, nRealLen) fp32. sourceIdx sorted.
// Single kernel. Per-CTA seq range via warp-cooperative 32-ary ballot search.
// Register accumulation (4 rows/warp), onset prefetch, smem transpose.
// Streaming cache hints: __ldcs on the zero-reuse TRF stream, __stcs on the
// write-once output stream. No atomics.

#define OUTD      128
#define TILE_T    32
#define ROWSTRIDE 132                 // (OUTD+4) floats, float4-aligned rows
#define NWARPS    8
#define NTHREADS  (NWARPS * 32)
#define ROWS_PW   (TILE_T / NWARPS)   // 4 rows per warp: tt = w + 8*r
#define CHUNK     64

// Warp-cooperative lower_bound: smallest i with a[i] >= v. All 32 lanes participate.
__device__ __forceinline__ int warp_lower_bound(const int* __restrict__ a,
                                                int n, int v, int lane)
{
    int lo = 0, hi = n;                       // answer in [lo, hi]
    while (hi - lo > 32) {
        const int chunk = (hi - lo + 32) / 33;
        const int p  = lo + (lane + 1) * chunk;
        const int pv = (p < hi) ? __ldg(a + p) : 0x7fffffff;
        const unsigned m = __ballot_sync(0xffffffffu, pv < v);
        const int c = __popc(m);              // probes strictly below v
        const int nlo = lo + c * chunk;
        hi = min(hi, nlo + chunk);
        lo = nlo;
    }
    const int p  = lo + lane;
    const int pv = (p < hi) ? __ldg(a + p) : 0x7fffffff;
    const unsigned m = __ballot_sync(0xffffffffu, pv < v);
    return lo + __popc(m);
}

__global__ __launch_bounds__(NTHREADS, 8) void trf_fold_kernel(
    const float4* __restrict__ TRF4,
    const int*    __restrict__ sIdx,
    float*        __restrict__ out,
    int nSeq, int nWin, int nRealLen)
{
    __shared__ float sm[TILE_T * ROWSTRIDE];
    __shared__ int   s_on[CHUNK];
    __shared__ int   s_range[2];

    const int t0   = blockIdx.x * TILE_T;
    const int tid  = threadIdx.x;
    const int w    = tid >> 5;
    const int lane = tid & 31;

    // ---- per-CTA range: warps 0 and 1 search concurrently (~3 ballot rounds each)
    if (w == 0) {
        int lo = warp_lower_bound(sIdx, nSeq, t0 - nWin + 1, lane);
        if (lane == 0) s_range[0] = lo;
    } else if (w == 1) {
        int hi = warp_lower_bound(sIdx, nSeq, t0 + TILE_T, lane);
        if (lane == 0) s_range[1] = hi;
    }
    __syncthreads();
    const int seqLo = s_range[0];
    const int seqHi = s_range[1];

    float4 acc[ROWS_PW];
    #pragma unroll
    for (int r = 0; r < ROWS_PW; ++r) acc[r] = make_float4(0.f, 0.f, 0.f, 0.f);

    const unsigned f4Row     = OUTD / 4;                 // 32 float4 per row
    const unsigned seqStride = (unsigned)nWin * f4Row;   // float4 per seq

    for (int cbase = seqLo; cbase < seqHi; cbase += CHUNK) {
        const int cn = min(seqHi - cbase, CHUNK);
        __syncthreads();                                 // protect s_on reuse
        if (tid < cn) s_on[tid] = sIdx[cbase + tid];
        __syncthreads();

        int s = s_on[0];                                 // prefetched onset
        for (int j = 0; j < cn; ++j) {
            const int sNext = (j + 1 < cn) ? s_on[j + 1] : 0;   // LDS off critical path
            const int kb = t0 + w - s;                   // k for row r: kb + 8r
            const unsigned off = (unsigned)(cbase + j) * seqStride
                               + (unsigned)kb * f4Row + (unsigned)lane;
            #pragma unroll
            for (int r = 0; r < ROWS_PW; ++r) {
                if ((unsigned)(kb + 8 * r) < (unsigned)nWin) {
                    float4 v = __ldcs(&TRF4[off + r * 8 * f4Row]); // LDG.128.CS [R+imm]
                    acc[r].x += v.x; acc[r].y += v.y;
                    acc[r].z += v.z; acc[r].w += v.w;
                }
            }
            s = sNext;
        }
    }

    // ---- one smem pass for the transpose ----
    #pragma unroll
    for (int r = 0; r < ROWS_PW; ++r)
        *reinterpret_cast<float4*>(sm + (w + 8 * r) * ROWSTRIDE + lane * 4) = acc[r];
    __syncthreads();

    // ---- coalesced streaming store: consecutive tid -> consecutive t per d-row ----
    #pragma unroll
    for (int idx = tid; idx < OUTD * TILE_T; idx += NTHREADS) {
        const int d  = idx >> 5;              // / TILE_T
        const int tt = idx & (TILE_T - 1);
        const int t  = t0 + tt;
        if (t < nRealLen)
            __stcs(&out[(size_t)d * nRealLen + t], sm[tt * ROWSTRIDE + d]);
    }
}

extern "C" void kernel_launch(void* const* d_in, const int* in_sizes, int n_in,
                              void* d_out, int out_size)
{
    const float4* TRF4 = (const float4*)d_in[0];
    const int*    sIdx = (const int*)d_in[1];
    const int nSeq     = in_sizes[1];
    const int nWin     = in_sizes[0] / (nSeq * OUTD);
    const int nRealLen = out_size / OUTD;

    const int grid = (nRealLen + TILE_T - 1) / TILE_T;
    trf_fold_kernel<<<grid, NTHREADS>>>(TRF4, sIdx, (float*)d_out,
                                        nSeq, nWin, nRealLen);
}

// round 9
// speedup vs baseline: 1.5510x; 1.0010x over previous
#include <cuda_runtime.h>

// TRFAligner: out[d, t] = sum over (seq, k) with sourceIdx[seq] + k == t of TRFs[seq, k, d]
// TRFs: (nSeq, nWin, OUTD) fp32; out: (OUTD, nRealLen) fp32. sourceIdx sorted.
// Single kernel, TILE_T=64 / 512 threads (16 warps, 4 rows each -> 16 acc regs).
// Per-CTA seq range via warp-cooperative 32-ary ballot search. Streaming hints.
// No atomics.

#define OUTD      128
#define TILE_T    64
#define ROWSTRIDE 132                 // (OUTD+4) floats, float4-aligned rows
#define NWARPS    16
#define NTHREADS  (NWARPS * 32)       // 512
#define ROWS_PW   (TILE_T / NWARPS)   // 4 rows per warp: tt = w + 16*r
#define CHUNK     64

// Warp-cooperative lower_bound: smallest i with a[i] >= v. All 32 lanes participate.
__device__ __forceinline__ int warp_lower_bound(const int* __restrict__ a,
                                                int n, int v, int lane)
{
    int lo = 0, hi = n;                       // answer in [lo, hi]
    while (hi - lo > 32) {
        const int chunk = (hi - lo + 32) / 33;
        const int p  = lo + (lane + 1) * chunk;
        const int pv = (p < hi) ? __ldg(a + p) : 0x7fffffff;
        const unsigned m = __ballot_sync(0xffffffffu, pv < v);
        const int c = __popc(m);              // probes strictly below v
        const int nlo = lo + c * chunk;
        hi = min(hi, nlo + chunk);
        lo = nlo;
    }
    const int p  = lo + lane;
    const int pv = (p < hi) ? __ldg(a + p) : 0x7fffffff;
    const unsigned m = __ballot_sync(0xffffffffu, pv < v);
    return lo + __popc(m);
}

__global__ __launch_bounds__(NTHREADS, 4) void trf_fold_kernel(
    const float4* __restrict__ TRF4,
    const int*    __restrict__ sIdx,
    float*        __restrict__ out,
    int nSeq, int nWin, int nRealLen)
{
    __shared__ float sm[TILE_T * ROWSTRIDE];
    __shared__ int   s_on[CHUNK];
    __shared__ int   s_range[2];

    const int t0   = blockIdx.x * TILE_T;
    const int tid  = threadIdx.x;
    const int w    = tid >> 5;
    const int lane = tid & 31;

    // ---- per-CTA range: warps 0 and 1 search concurrently (~3 ballot rounds each)
    if (w == 0) {
        int lo = warp_lower_bound(sIdx, nSeq, t0 - nWin + 1, lane);
        if (lane == 0) s_range[0] = lo;
    } else if (w == 1) {
        int hi = warp_lower_bound(sIdx, nSeq, t0 + TILE_T, lane);
        if (lane == 0) s_range[1] = hi;
    }
    __syncthreads();
    const int seqLo = s_range[0];
    const int seqHi = s_range[1];

    float4 acc[ROWS_PW];
    #pragma unroll
    for (int r = 0; r < ROWS_PW; ++r) acc[r] = make_float4(0.f, 0.f, 0.f, 0.f);

    const unsigned f4Row     = OUTD / 4;                 // 32 float4 per row
    const unsigned seqStride = (unsigned)nWin * f4Row;   // float4 per seq

    for (int cbase = seqLo; cbase < seqHi; cbase += CHUNK) {
        const int cn = min(seqHi - cbase, CHUNK);
        __syncthreads();                                 // protect s_on reuse
        if (tid < cn) s_on[tid] = sIdx[cbase + tid];
        __syncthreads();

        int s = s_on[0];                                 // prefetched onset
        for (int j = 0; j < cn; ++j) {
            const int sNext = (j + 1 < cn) ? s_on[j + 1] : 0;   // LDS off critical path
            const int kb = t0 + w - s;                   // k for row r: kb + 16r
            const unsigned off = (unsigned)(cbase + j) * seqStride
                               + (unsigned)kb * f4Row + (unsigned)lane;
            #pragma unroll
            for (int r = 0; r < ROWS_PW; ++r) {
                if ((unsigned)(kb + NWARPS * r) < (unsigned)nWin) {
                    float4 v = __ldcs(&TRF4[off + r * NWARPS * f4Row]); // LDG.128.CS [R+imm]
                    acc[r].x += v.x; acc[r].y += v.y;
                    acc[r].z += v.z; acc[r].w += v.w;
                }
            }
            s = sNext;
        }
    }

    // ---- one smem pass for the transpose ----
    #pragma unroll
    for (int r = 0; r < ROWS_PW; ++r)
        *reinterpret_cast<float4*>(sm + (w + NWARPS * r) * ROWSTRIDE + lane * 4) = acc[r];
    __syncthreads();

    // ---- coalesced streaming store: consecutive tid -> consecutive t per d-row ----
    #pragma unroll
    for (int idx = tid; idx < OUTD * TILE_T; idx += NTHREADS) {
        const int d  = idx >> 6;              // / TILE_T
        const int tt = idx & (TILE_T - 1);
        const int t  = t0 + tt;
        if (t < nRealLen)
            __stcs(&out[(size_t)d * nRealLen + t], sm[tt * ROWSTRIDE + d]);
    }
}

extern "C" void kernel_launch(void* const* d_in, const int* in_sizes, int n_in,
                              void* d_out, int out_size)
{
    const float4* TRF4 = (const float4*)d_in[0];
    const int*    sIdx = (const int*)d_in[1];
    const int nSeq     = in_sizes[1];
    const int nWin     = in_sizes[0] / (nSeq * OUTD);
    const int nRealLen = out_size / OUTD;

    const int grid = (nRealLen + TILE_T - 1) / TILE_T;
    trf_fold_kernel<<<grid, NTHREADS>>>(TRF4, sIdx, (float*)d_out,
                                        nSeq, nWin, nRealLen);
}

// round 10
// speedup vs baseline: 1.7122x; 1.1039x over previous
#include <cuda_runtime.h>

// TRFAligner: out[d, t] = sum over (seq, k) with sourceIdx[seq] + k == t of TRFs[seq, k, d]
// TRFs: (nSeq, nWin, OUTD) fp32; out: (OUTD, nRealLen) fp32. sourceIdx sorted.
// Single kernel, TILE_T=32 / 256 threads (8 warps, 4 rows each).
// launch_bounds(256,6): ~42 regs so ptxas can double-buffer the 4 loads per
// iteration (front-batched LDG.128, MLP_p1=4) instead of serializing on scratch
// registers. Warp-cooperative ballot search for the seq range. No atomics.

#define OUTD      128
#define TILE_T    32
#define ROWSTRIDE 132                 // (OUTD+4) floats, float4-aligned rows
#define NWARPS    8
#define NTHREADS  (NWARPS * 32)
#define ROWS_PW   (TILE_T / NWARPS)   // 4 rows per warp: tt = w + 8*r
#define CHUNK     64

// Warp-cooperative lower_bound: smallest i with a[i] >= v. All 32 lanes participate.
__device__ __forceinline__ int warp_lower_bound(const int* __restrict__ a,
                                                int n, int v, int lane)
{
    int lo = 0, hi = n;                       // answer in [lo, hi]
    while (hi - lo > 32) {
        const int chunk = (hi - lo + 32) / 33;
        const int p  = lo + (lane + 1) * chunk;
        const int pv = (p < hi) ? __ldg(a + p) : 0x7fffffff;
        const unsigned m = __ballot_sync(0xffffffffu, pv < v);
        const int c = __popc(m);              // probes strictly below v
        const int nlo = lo + c * chunk;
        hi = min(hi, nlo + chunk);
        lo = nlo;
    }
    const int p  = lo + lane;
    const int pv = (p < hi) ? __ldg(a + p) : 0x7fffffff;
    const unsigned m = __ballot_sync(0xffffffffu, pv < v);
    return lo + __popc(m);
}

__global__ __launch_bounds__(NTHREADS, 6) void trf_fold_kernel(
    const float4* __restrict__ TRF4,
    const int*    __restrict__ sIdx,
    float*        __restrict__ out,
    int nSeq, int nWin, int nRealLen)
{
    __shared__ float sm[TILE_T * ROWSTRIDE];
    __shared__ int   s_on[CHUNK];
    __shared__ int   s_range[2];

    const int t0   = blockIdx.x * TILE_T;
    const int tid  = threadIdx.x;
    const int w    = tid >> 5;
    const int lane = tid & 31;

    // ---- per-CTA range: warps 0 and 1 search concurrently (~3 ballot rounds each)
    if (w == 0) {
        int lo = warp_lower_bound(sIdx, nSeq, t0 - nWin + 1, lane);
        if (lane == 0) s_range[0] = lo;
    } else if (w == 1) {
        int hi = warp_lower_bound(sIdx, nSeq, t0 + TILE_T, lane);
        if (lane == 0) s_range[1] = hi;
    }
    __syncthreads();
    const int seqLo = s_range[0];
    const int seqHi = s_range[1];

    float4 acc[ROWS_PW];
    #pragma unroll
    for (int r = 0; r < ROWS_PW; ++r) acc[r] = make_float4(0.f, 0.f, 0.f, 0.f);

    const unsigned f4Row     = OUTD / 4;                 // 32 float4 per row
    const unsigned seqStride = (unsigned)nWin * f4Row;   // float4 per seq

    for (int cbase = seqLo; cbase < seqHi; cbase += CHUNK) {
        const int cn = min(seqHi - cbase, CHUNK);
        __syncthreads();                                 // protect s_on reuse
        if (tid < cn) s_on[tid] = sIdx[cbase + tid];
        __syncthreads();

        int s = s_on[0];                                 // prefetched onset
        for (int j = 0; j < cn; ++j) {
            const int sNext = (j + 1 < cn) ? s_on[j + 1] : 0;   // LDS off critical path
            const int kb = t0 + w - s;                   // k for row r: kb + 8r
            const unsigned off = (unsigned)(cbase + j) * seqStride
                               + (unsigned)kb * f4Row + (unsigned)lane;

            // Phase 1: issue all 4 predicated loads (front-batched LDG.128 [R+imm])
            float4 v[ROWS_PW];
            bool   p[ROWS_PW];
            #pragma unroll
            for (int r = 0; r < ROWS_PW; ++r) {
                p[r] = (unsigned)(kb + 8 * r) < (unsigned)nWin;
                v[r] = make_float4(0.f, 0.f, 0.f, 0.f);
                if (p[r]) v[r] = __ldcs(&TRF4[off + r * 8 * f4Row]);
            }
            // Phase 2: accumulate
            #pragma unroll
            for (int r = 0; r < ROWS_PW; ++r) {
                if (p[r]) {
                    acc[r].x += v[r].x; acc[r].y += v[r].y;
                    acc[r].z += v[r].z; acc[r].w += v[r].w;
                }
            }
            s = sNext;
        }
    }

    // ---- one smem pass for the transpose ----
    #pragma unroll
    for (int r = 0; r < ROWS_PW; ++r)
        *reinterpret_cast<float4*>(sm + (w + 8 * r) * ROWSTRIDE + lane * 4) = acc[r];
    __syncthreads();

    // ---- coalesced streaming store: consecutive tid -> consecutive t per d-row ----
    #pragma unroll
    for (int idx = tid; idx < OUTD * TILE_T; idx += NTHREADS) {
        const int d  = idx >> 5;              // / TILE_T
        const int tt = idx & (TILE_T - 1);
        const int t  = t0 + tt;
        if (t < nRealLen)
            __stcs(&out[(size_t)d * nRealLen + t], sm[tt * ROWSTRIDE + d]);
    }
}

extern "C" void kernel_launch(void* const* d_in, const int* in_sizes, int n_in,
                              void* d_out, int out_size)
{
    const float4* TRF4 = (const float4*)d_in[0];
    const int*    sIdx = (const int*)d_in[1];
    const int nSeq     = in_sizes[1];
    const int nWin     = in_sizes[0] / (nSeq * OUTD);
    const int nRealLen = out_size / OUTD;

    const int grid = (nRealLen + TILE_T - 1) / TILE_T;
    trf_fold_kernel<<<grid, NTHREADS>>>(TRF4, sIdx, (float*)d_out,
                                        nSeq, nWin, nRealLen);
}